// round 1
// baseline (speedup 1.0000x reference)
#include <cuda_runtime.h>
#include <math.h>

#define NN 100000
#define NE 1600000
#define DIM 128

// ---- scratch (device globals: no allocation allowed) ----
__device__ float g_xs[NN*DIM];    // source-side projection x@Wsrc
__device__ float g_h [NN*DIM];    // skip (x@linW+lin_b), later h
__device__ float g_agg[NN*DIM];   // unnormalized message aggregate
__device__ float g_x [NN*DIM];    // layer output ping buffer
__device__ float g_s [NN*8];      // per-node attention scores [ssrc0..3, sdst0..3]
__device__ float g_den[NN*4];     // softmax denominators per head
__device__ float g_B [DIM*256];   // packed [Wsrc | linW]
__device__ float g_Batt[8*DIM];   // packed (W @ att) vectors, transposed
__device__ float g_bn [2*DIM];    // per-channel sum / sumsq

// ---- pack per-layer weights ----
__global__ void pack_weights(const float* __restrict__ Wsrc,
                             const float* __restrict__ Wdst,
                             const float* __restrict__ linW,
                             const float* __restrict__ asrc,
                             const float* __restrict__ adst) {
  int idx = blockIdx.x*blockDim.x + threadIdx.x;
  if (idx < DIM*256) {
    int k = idx >> 8, j = idx & 255;
    g_B[idx] = (j < 128) ? Wsrc[k*128 + j] : linW[k*128 + (j-128)];
  } else if (idx < DIM*256 + 8*DIM) {
    int r = idx - DIM*256;
    int t = r >> 7, k = r & 127;
    int h = t & 3;
    const float* W = (t < 4) ? Wsrc : Wdst;
    const float* a = (t < 4) ? asrc : adst;
    float s = 0.f;
    #pragma unroll
    for (int c = 0; c < 32; c++) s += W[k*128 + h*32 + c] * a[h*32 + c];
    g_Batt[t*128 + k] = s;
  }
}

// ---- fp32 SGEMM: 128x128 tile, 8x8 per thread, K=128 ----
// mode 0: C[r*NC+c] = acc + bias[c]
// mode 1: cols<128 -> g_xs ; cols>=128 -> g_h (+bias[c-128])
__global__ void __launch_bounds__(256) sgemm(
    const float* __restrict__ A, const float* __restrict__ B,
    float* __restrict__ C, int M, int NC,
    const float* __restrict__ bias, int mode)
{
  __shared__ float As[16][128];
  __shared__ float Bs[16][128];
  const int tid = threadIdx.x;
  const int m0 = blockIdx.y * 128;
  const int n0 = blockIdx.x * 128;
  const int ty = tid >> 4, tx = tid & 15;

  float acc[8][8];
#pragma unroll
  for (int i = 0; i < 8; i++)
#pragma unroll
    for (int j = 0; j < 8; j++) acc[i][j] = 0.f;

  const int aRow = tid >> 1;
  const int aK   = (tid & 1) * 8;
  const int bRow = tid >> 4;
  const int bCol = (tid & 15) * 8;

  for (int k0 = 0; k0 < 128; k0 += 16) {
    float4 a0, a1;
    if (m0 + aRow < M) {
      const float* ap = A + (size_t)(m0 + aRow)*128 + k0 + aK;
      a0 = *(const float4*)ap; a1 = *(const float4*)(ap + 4);
    } else { a0 = make_float4(0,0,0,0); a1 = a0; }
    As[aK+0][aRow]=a0.x; As[aK+1][aRow]=a0.y; As[aK+2][aRow]=a0.z; As[aK+3][aRow]=a0.w;
    As[aK+4][aRow]=a1.x; As[aK+5][aRow]=a1.y; As[aK+6][aRow]=a1.z; As[aK+7][aRow]=a1.w;

    const float* bp = B + (size_t)(k0 + bRow)*NC + n0 + bCol;
    float bv[8];
#pragma unroll
    for (int q = 0; q < 8; q++)
      bv[q] = (n0 + bCol + q < NC) ? bp[q] : 0.f;
    Bs[bRow][bCol+0]=bv[0]; Bs[bRow][bCol+1]=bv[1]; Bs[bRow][bCol+2]=bv[2]; Bs[bRow][bCol+3]=bv[3];
    Bs[bRow][bCol+4]=bv[4]; Bs[bRow][bCol+5]=bv[5]; Bs[bRow][bCol+6]=bv[6]; Bs[bRow][bCol+7]=bv[7];
    __syncthreads();

#pragma unroll
    for (int k = 0; k < 16; k++) {
      float av[8], bw[8];
      float4 t0 = *(const float4*)&As[k][ty*8];
      float4 t1 = *(const float4*)&As[k][ty*8+4];
      float4 u0 = *(const float4*)&Bs[k][tx*8];
      float4 u1 = *(const float4*)&Bs[k][tx*8+4];
      av[0]=t0.x; av[1]=t0.y; av[2]=t0.z; av[3]=t0.w;
      av[4]=t1.x; av[5]=t1.y; av[6]=t1.z; av[7]=t1.w;
      bw[0]=u0.x; bw[1]=u0.y; bw[2]=u0.z; bw[3]=u0.w;
      bw[4]=u1.x; bw[5]=u1.y; bw[6]=u1.z; bw[7]=u1.w;
#pragma unroll
      for (int i = 0; i < 8; i++)
#pragma unroll
        for (int j = 0; j < 8; j++)
          acc[i][j] = fmaf(av[i], bw[j], acc[i][j]);
    }
    __syncthreads();
  }

#pragma unroll
  for (int i = 0; i < 8; i++) {
    int r = m0 + ty*8 + i;
    if (r >= M) continue;
#pragma unroll
    for (int j = 0; j < 8; j++) {
      int c = n0 + tx*8 + j;
      if (c >= NC) continue;
      float v = acc[i][j];
      if (mode == 0) {
        C[(size_t)r*NC + c] = v + bias[c];
      } else {
        if (c < 128) g_xs[(size_t)r*128 + c] = v;
        else         g_h [(size_t)r*128 + (c-128)] = v + bias[c-128];
      }
    }
  }
}

// ---- per-node attention scores: s[n,t] = x[n,:] @ g_Batt[t,:] ----
__global__ void __launch_bounds__(256) att_scores(const float* __restrict__ X) {
  int gw = (blockIdx.x*blockDim.x + threadIdx.x) >> 5;
  if (gw >= NN) return;
  int lane = threadIdx.x & 31;
  float4 xv = *(const float4*)&X[(size_t)gw*128 + lane*4];
#pragma unroll
  for (int t = 0; t < 8; t++) {
    float4 w = *(const float4*)&g_Batt[t*128 + lane*4];
    float p = xv.x*w.x + xv.y*w.y + xv.z*w.z + xv.w*w.w;
#pragma unroll
    for (int off = 16; off; off >>= 1) p += __shfl_xor_sync(0xffffffffu, p, off);
    if (lane == 0) g_s[(size_t)gw*8 + t] = p;
  }
}

__global__ void zero_bufs() {
  int i = blockIdx.x*blockDim.x + threadIdx.x;
  float4 z = make_float4(0,0,0,0);
  if (i < NN*32) ((float4*)g_agg)[i] = z;
  if (i < NN)    ((float4*)g_den)[i] = z;
  if (i < 64)    ((float4*)g_bn)[i]  = z;
}

// ---- edge pass: softmax numerators + weighted scatter (no max pass: logits O(1)) ----
__global__ void __launch_bounds__(256) edge_pass(const int* __restrict__ src,
                                                 const int* __restrict__ dst) {
  int e = (blockIdx.x*blockDim.x + threadIdx.x) >> 5;
  if (e >= NE) return;
  int lane = threadIdx.x & 31;
  int s = __ldg(&src[e]);
  int d = __ldg(&dst[e]);
  int head = lane >> 3;
  float ev = g_s[(size_t)s*8 + head] + g_s[(size_t)d*8 + 4 + head];
  ev = (ev > 0.f) ? ev : 0.2f*ev;
  float p = __expf(ev);
  if ((lane & 7) == 0) atomicAdd(&g_den[(size_t)d*4 + head], p);
  float4 v = *(const float4*)&g_xs[(size_t)s*128 + lane*4];
  float* ap = &g_agg[(size_t)d*128 + lane*4];
  atomicAdd(ap+0, v.x*p);
  atomicAdd(ap+1, v.y*p);
  atomicAdd(ap+2, v.z*p);
  atomicAdd(ap+3, v.w*p);
}

// ---- combine: h = agg/den + conv_bias + skip ; accumulate BN stats ----
__global__ void __launch_bounds__(256) combine(const float* __restrict__ cbias) {
  __shared__ float s_sum[128], s_sq[128];
  int tid = threadIdx.x;
  if (tid < 128) { s_sum[tid] = 0.f; s_sq[tid] = 0.f; }
  __syncthreads();
  int lane = tid & 31, sub = tid >> 5;
  int c4 = lane*4, head = lane >> 3;
  float4 cb = *(const float4*)&cbias[c4];
  float ls0=0,ls1=0,ls2=0,ls3=0, lq0=0,lq1=0,lq2=0,lq3=0;
  for (int it = 0; it < 8; it++) {
    int n = blockIdx.x*64 + it*8 + sub;
    if (n < NN) {
      float inv = 1.f / (g_den[(size_t)n*4 + head] + 1e-16f);
      float4 a  = *(const float4*)&g_agg[(size_t)n*128 + c4];
      float4 sk = *(const float4*)&g_h [(size_t)n*128 + c4];
      float h0 = a.x*inv + cb.x + sk.x;
      float h1 = a.y*inv + cb.y + sk.y;
      float h2 = a.z*inv + cb.z + sk.z;
      float h3 = a.w*inv + cb.w + sk.w;
      *(float4*)&g_h[(size_t)n*128 + c4] = make_float4(h0,h1,h2,h3);
      ls0+=h0; ls1+=h1; ls2+=h2; ls3+=h3;
      lq0+=h0*h0; lq1+=h1*h1; lq2+=h2*h2; lq3+=h3*h3;
    }
  }
  atomicAdd(&s_sum[c4+0], ls0); atomicAdd(&s_sum[c4+1], ls1);
  atomicAdd(&s_sum[c4+2], ls2); atomicAdd(&s_sum[c4+3], ls3);
  atomicAdd(&s_sq[c4+0], lq0);  atomicAdd(&s_sq[c4+1], lq1);
  atomicAdd(&s_sq[c4+2], lq2);  atomicAdd(&s_sq[c4+3], lq3);
  __syncthreads();
  if (tid < 128) {
    atomicAdd(&g_bn[tid],       s_sum[tid]);
    atomicAdd(&g_bn[128 + tid], s_sq[tid]);
  }
}

// ---- batchnorm + relu ----
__global__ void __launch_bounds__(256) bn_relu(const float* __restrict__ gamma,
                                               const float* __restrict__ beta,
                                               float* __restrict__ XO) {
  int idx = blockIdx.x*blockDim.x + threadIdx.x;
  if (idx >= NN*32) return;
  int c4 = (idx & 31) * 4;
  const float invN = 1.f / (float)NN;
  float4 h = *(const float4*)&g_h[(size_t)idx*4];
  float hv[4] = {h.x, h.y, h.z, h.w};
  float ov[4];
#pragma unroll
  for (int k = 0; k < 4; k++) {
    int c = c4 + k;
    float mu  = g_bn[c] * invN;
    float var = g_bn[128 + c] * invN - mu*mu;
    float sc  = gamma[c] * rsqrtf(var + 1e-5f);
    float sh  = beta[c] - mu*sc;
    float v = hv[k]*sc + sh;
    ov[k] = v > 0.f ? v : 0.f;
  }
  *(float4*)&XO[(size_t)idx*4] = make_float4(ov[0],ov[1],ov[2],ov[3]);
}

extern "C" void kernel_launch(void* const* d_in, const int* in_sizes, int n_in,
                              void* d_out, int out_size) {
  const float* x0    = (const float*)d_in[0];
  const int*   ei    = (const int*)  d_in[1];
  const float* Wsrc  = (const float*)d_in[2];
  const float* Wdst  = (const float*)d_in[3];
  const float* asrc  = (const float*)d_in[4];
  const float* adst  = (const float*)d_in[5];
  const float* cbias = (const float*)d_in[6];
  const float* linW  = (const float*)d_in[7];
  const float* linb  = (const float*)d_in[8];
  const float* gamma = (const float*)d_in[9];
  const float* beta  = (const float*)d_in[10];
  const float* fcW   = (const float*)d_in[11];
  const float* fcb   = (const float*)d_in[12];
  float* out = (float*)d_out;

  float *xg = 0, *Bg = 0;
  cudaGetSymbolAddress((void**)&xg, g_x);
  cudaGetSymbolAddress((void**)&Bg, g_B);

  const int* src = ei;
  const int* dst = ei + NE;

  for (int i = 0; i < 2; i++) {
    const float* xin = (i == 0) ? x0 : xg;
    pack_weights<<<132, 256>>>(Wsrc + i*16384, Wdst + i*16384, linW + i*16384,
                               asrc + i*128, adst + i*128);
    sgemm<<<dim3(2, 782), 256>>>(xin, Bg, nullptr, NN, 256, linb + i*128, 1);
    att_scores<<<12500, 256>>>(xin);
    zero_bufs<<<12500, 256>>>();
    edge_pass<<<200000, 256>>>(src, dst);
    combine<<<1563, 256>>>(cbias + i*128);
    bn_relu<<<12500, 256>>>(gamma + i*128, beta + i*128, xg);
  }
  sgemm<<<dim3(3, 782), 256>>>(xg, fcW, out, NN, 349, fcb, 0);
}

// round 2
// speedup vs baseline: 1.2746x; 1.2746x over previous
#include <cuda_runtime.h>
#include <math.h>

#define NN 100000
#define NE 1600000
#define DIM 128

typedef unsigned long long ull;

// ---- scratch (device globals: no allocation allowed) ----
__device__ float g_xs[NN*DIM];    // source-side projection x@Wsrc
__device__ float g_h [NN*DIM];    // skip (x@linW+lin_b), later h
__device__ float g_agg[NN*DIM];   // unnormalized message aggregate
__device__ float g_x [NN*DIM];    // layer output ping buffer
__device__ float g_s [NN*8];      // per-node attention scores [ssrc0..3, sdst0..3]
__device__ float g_den[NN*4];     // softmax denominators per head
__device__ float g_B [DIM*256];   // packed [Wsrc | linW]
__device__ float g_Batt[8*DIM];   // packed (W @ att) vectors, transposed
__device__ float g_bn [2*DIM];    // per-channel sum / sumsq

__device__ __forceinline__ void ffma2(ull &d, ull a, ull b) {
  asm volatile("fma.rn.f32x2 %0, %1, %2, %0;" : "+l"(d) : "l"(a), "l"(b));
}
__device__ __forceinline__ ull dup2(float v) {
  ull r; asm("mov.b64 %0, {%1, %1};" : "=l"(r) : "f"(v)); return r;
}
__device__ __forceinline__ void unpack2(float &lo, float &hi, ull v) {
  asm("mov.b64 {%0, %1}, %2;" : "=f"(lo), "=f"(hi) : "l"(v));
}

// ---- pack per-layer weights ----
__global__ void pack_weights(const float* __restrict__ Wsrc,
                             const float* __restrict__ Wdst,
                             const float* __restrict__ linW,
                             const float* __restrict__ asrc,
                             const float* __restrict__ adst) {
  int idx = blockIdx.x*blockDim.x + threadIdx.x;
  if (idx < DIM*256) {
    int k = idx >> 8, j = idx & 255;
    g_B[idx] = (j < 128) ? Wsrc[k*128 + j] : linW[k*128 + (j-128)];
  } else if (idx < DIM*256 + 8*DIM) {
    int r = idx - DIM*256;
    int t = r >> 7, k = r & 127;
    int h = t & 3;
    const float* W = (t < 4) ? Wsrc : Wdst;
    const float* a = (t < 4) ? asrc : adst;
    float s = 0.f;
    #pragma unroll
    for (int c = 0; c < 32; c++) s += W[k*128 + h*32 + c] * a[h*32 + c];
    g_Batt[t*128 + k] = s;
  }
}

// ---- fp32 SGEMM via packed fma.rn.f32x2: 128x128 tile, 8x8 per thread ----
// mode 0: C[r*NC+c] = acc + bias[c]
// mode 1: cols<128 -> g_xs ; cols>=128 -> g_h (+bias[c-128])
__global__ void __launch_bounds__(256) sgemm(
    const float* __restrict__ A, const float* __restrict__ B,
    float* __restrict__ C, int M, int NC,
    const float* __restrict__ bias, int mode)
{
  __shared__ float As[16][128];
  __shared__ float Bs[16][128];
  const int tid = threadIdx.x;
  const int m0 = blockIdx.y * 128;
  const int n0 = blockIdx.x * 128;
  const int ty = tid >> 4, tx = tid & 15;

  ull acc2[8][4];
#pragma unroll
  for (int i = 0; i < 8; i++)
#pragma unroll
    for (int j = 0; j < 4; j++) acc2[i][j] = 0ull;

  const int aRow = tid >> 1;
  const int aK   = (tid & 1) * 8;
  const int bRow = tid >> 4;
  const int bCol = (tid & 15) * 8;

  for (int k0 = 0; k0 < 128; k0 += 16) {
    float4 a0, a1;
    if (m0 + aRow < M) {
      const float* ap = A + (size_t)(m0 + aRow)*128 + k0 + aK;
      a0 = *(const float4*)ap; a1 = *(const float4*)(ap + 4);
    } else { a0 = make_float4(0,0,0,0); a1 = a0; }
    As[aK+0][aRow]=a0.x; As[aK+1][aRow]=a0.y; As[aK+2][aRow]=a0.z; As[aK+3][aRow]=a0.w;
    As[aK+4][aRow]=a1.x; As[aK+5][aRow]=a1.y; As[aK+6][aRow]=a1.z; As[aK+7][aRow]=a1.w;

    const float* bp = B + (size_t)(k0 + bRow)*NC + n0 + bCol;
    float bv[8];
#pragma unroll
    for (int q = 0; q < 8; q++)
      bv[q] = (n0 + bCol + q < NC) ? bp[q] : 0.f;
    Bs[bRow][bCol+0]=bv[0]; Bs[bRow][bCol+1]=bv[1]; Bs[bRow][bCol+2]=bv[2]; Bs[bRow][bCol+3]=bv[3];
    Bs[bRow][bCol+4]=bv[4]; Bs[bRow][bCol+5]=bv[5]; Bs[bRow][bCol+6]=bv[6]; Bs[bRow][bCol+7]=bv[7];
    __syncthreads();

#pragma unroll
    for (int k = 0; k < 16; k++) {
      float4 t0 = *(const float4*)&As[k][ty*8];
      float4 t1 = *(const float4*)&As[k][ty*8+4];
      ull a2[8];
      a2[0]=dup2(t0.x); a2[1]=dup2(t0.y); a2[2]=dup2(t0.z); a2[3]=dup2(t0.w);
      a2[4]=dup2(t1.x); a2[5]=dup2(t1.y); a2[6]=dup2(t1.z); a2[7]=dup2(t1.w);
      ull bw2[4];
      bw2[0] = *(const ull*)&Bs[k][tx*8 + 0];
      bw2[1] = *(const ull*)&Bs[k][tx*8 + 2];
      bw2[2] = *(const ull*)&Bs[k][tx*8 + 4];
      bw2[3] = *(const ull*)&Bs[k][tx*8 + 6];
#pragma unroll
      for (int i = 0; i < 8; i++)
#pragma unroll
        for (int j = 0; j < 4; j++)
          ffma2(acc2[i][j], a2[i], bw2[j]);
    }
    __syncthreads();
  }

#pragma unroll
  for (int i = 0; i < 8; i++) {
    int r = m0 + ty*8 + i;
    if (r >= M) continue;
#pragma unroll
    for (int j = 0; j < 4; j++) {
      float vlo, vhi;
      unpack2(vlo, vhi, acc2[i][j]);
      int c = n0 + tx*8 + 2*j;
#pragma unroll
      for (int q = 0; q < 2; q++) {
        int cc = c + q;
        if (cc >= NC) continue;
        float v = q ? vhi : vlo;
        if (mode == 0) {
          C[(size_t)r*NC + cc] = v + bias[cc];
        } else {
          if (cc < 128) g_xs[(size_t)r*128 + cc] = v;
          else          g_h [(size_t)r*128 + (cc-128)] = v + bias[cc-128];
        }
      }
    }
  }
}

// ---- per-node attention scores: s[n,t] = x[n,:] @ g_Batt[t,:] ----
__global__ void __launch_bounds__(256) att_scores(const float* __restrict__ X) {
  int gw = (blockIdx.x*blockDim.x + threadIdx.x) >> 5;
  if (gw >= NN) return;
  int lane = threadIdx.x & 31;
  float4 xv = *(const float4*)&X[(size_t)gw*128 + lane*4];
#pragma unroll
  for (int t = 0; t < 8; t++) {
    float4 w = *(const float4*)&g_Batt[t*128 + lane*4];
    float p = xv.x*w.x + xv.y*w.y + xv.z*w.z + xv.w*w.w;
#pragma unroll
    for (int off = 16; off; off >>= 1) p += __shfl_xor_sync(0xffffffffu, p, off);
    if (lane == 0) g_s[(size_t)gw*8 + t] = p;
  }
}

__global__ void zero_bufs() {
  int i = blockIdx.x*blockDim.x + threadIdx.x;
  float4 z = make_float4(0,0,0,0);
  if (i < NN*32) ((float4*)g_agg)[i] = z;
  if (i < NN)    ((float4*)g_den)[i] = z;
  if (i < 64)    ((float4*)g_bn)[i]  = z;
}

// ---- edge pass: softmax numerators + weighted scatter via red.v4 ----
__global__ void __launch_bounds__(256) edge_pass(const int* __restrict__ src,
                                                 const int* __restrict__ dst) {
  int e = (blockIdx.x*blockDim.x + threadIdx.x) >> 5;
  if (e >= NE) return;
  int lane = threadIdx.x & 31;
  int s = __ldg(&src[e]);
  int d = __ldg(&dst[e]);
  int head = lane >> 3;
  float ev = g_s[(size_t)s*8 + head] + g_s[(size_t)d*8 + 4 + head];
  ev = (ev > 0.f) ? ev : 0.2f*ev;
  float p = __expf(ev);
  if ((lane & 7) == 0) atomicAdd(&g_den[(size_t)d*4 + head], p);
  float4 v = *(const float4*)&g_xs[(size_t)s*128 + lane*4];
  float* ap = &g_agg[(size_t)d*128 + lane*4];
  asm volatile("red.global.add.v4.f32 [%0], {%1, %2, %3, %4};"
               :: "l"(ap), "f"(v.x*p), "f"(v.y*p), "f"(v.z*p), "f"(v.w*p)
               : "memory");
}

// ---- combine: h = agg/den + conv_bias + skip ; accumulate BN stats ----
__global__ void __launch_bounds__(256) combine(const float* __restrict__ cbias) {
  __shared__ float s_sum[128], s_sq[128];
  int tid = threadIdx.x;
  if (tid < 128) { s_sum[tid] = 0.f; s_sq[tid] = 0.f; }
  __syncthreads();
  int lane = tid & 31, sub = tid >> 5;
  int c4 = lane*4, head = lane >> 3;
  float4 cb = *(const float4*)&cbias[c4];
  float ls0=0,ls1=0,ls2=0,ls3=0, lq0=0,lq1=0,lq2=0,lq3=0;
  for (int it = 0; it < 8; it++) {
    int n = blockIdx.x*64 + it*8 + sub;
    if (n < NN) {
      float inv = 1.f / (g_den[(size_t)n*4 + head] + 1e-16f);
      float4 a  = *(const float4*)&g_agg[(size_t)n*128 + c4];
      float4 sk = *(const float4*)&g_h [(size_t)n*128 + c4];
      float h0 = a.x*inv + cb.x + sk.x;
      float h1 = a.y*inv + cb.y + sk.y;
      float h2 = a.z*inv + cb.z + sk.z;
      float h3 = a.w*inv + cb.w + sk.w;
      *(float4*)&g_h[(size_t)n*128 + c4] = make_float4(h0,h1,h2,h3);
      ls0+=h0; ls1+=h1; ls2+=h2; ls3+=h3;
      lq0+=h0*h0; lq1+=h1*h1; lq2+=h2*h2; lq3+=h3*h3;
    }
  }
  atomicAdd(&s_sum[c4+0], ls0); atomicAdd(&s_sum[c4+1], ls1);
  atomicAdd(&s_sum[c4+2], ls2); atomicAdd(&s_sum[c4+3], ls3);
  atomicAdd(&s_sq[c4+0], lq0);  atomicAdd(&s_sq[c4+1], lq1);
  atomicAdd(&s_sq[c4+2], lq2);  atomicAdd(&s_sq[c4+3], lq3);
  __syncthreads();
  if (tid < 128) {
    atomicAdd(&g_bn[tid],       s_sum[tid]);
    atomicAdd(&g_bn[128 + tid], s_sq[tid]);
  }
}

// ---- batchnorm + relu ----
__global__ void __launch_bounds__(256) bn_relu(const float* __restrict__ gamma,
                                               const float* __restrict__ beta,
                                               float* __restrict__ XO) {
  int idx = blockIdx.x*blockDim.x + threadIdx.x;
  if (idx >= NN*32) return;
  int c4 = (idx & 31) * 4;
  const float invN = 1.f / (float)NN;
  float4 h = *(const float4*)&g_h[(size_t)idx*4];
  float hv[4] = {h.x, h.y, h.z, h.w};
  float ov[4];
#pragma unroll
  for (int k = 0; k < 4; k++) {
    int c = c4 + k;
    float mu  = g_bn[c] * invN;
    float var = g_bn[128 + c] * invN - mu*mu;
    float sc  = gamma[c] * rsqrtf(var + 1e-5f);
    float sh  = beta[c] - mu*sc;
    float v = hv[k]*sc + sh;
    ov[k] = v > 0.f ? v : 0.f;
  }
  *(float4*)&XO[(size_t)idx*4] = make_float4(ov[0],ov[1],ov[2],ov[3]);
}

extern "C" void kernel_launch(void* const* d_in, const int* in_sizes, int n_in,
                              void* d_out, int out_size) {
  const float* x0    = (const float*)d_in[0];
  const int*   ei    = (const int*)  d_in[1];
  const float* Wsrc  = (const float*)d_in[2];
  const float* Wdst  = (const float*)d_in[3];
  const float* asrc  = (const float*)d_in[4];
  const float* adst  = (const float*)d_in[5];
  const float* cbias = (const float*)d_in[6];
  const float* linW  = (const float*)d_in[7];
  const float* linb  = (const float*)d_in[8];
  const float* gamma = (const float*)d_in[9];
  const float* beta  = (const float*)d_in[10];
  const float* fcW   = (const float*)d_in[11];
  const float* fcb   = (const float*)d_in[12];
  float* out = (float*)d_out;

  float *xg = 0, *Bg = 0;
  cudaGetSymbolAddress((void**)&xg, g_x);
  cudaGetSymbolAddress((void**)&Bg, g_B);

  const int* src = ei;
  const int* dst = ei + NE;

  for (int i = 0; i < 2; i++) {
    const float* xin = (i == 0) ? x0 : xg;
    pack_weights<<<132, 256>>>(Wsrc + i*16384, Wdst + i*16384, linW + i*16384,
                               asrc + i*128, adst + i*128);
    sgemm<<<dim3(2, 782), 256>>>(xin, Bg, nullptr, NN, 256, linb + i*128, 1);
    att_scores<<<12500, 256>>>(xin);
    zero_bufs<<<12500, 256>>>();
    edge_pass<<<200000, 256>>>(src, dst);
    combine<<<1563, 256>>>(cbias + i*128);
    bn_relu<<<12500, 256>>>(gamma + i*128, beta + i*128, xg);
  }
  sgemm<<<dim3(3, 782), 256>>>(xg, fcW, out, NN, 349, fcb, 0);
}

// round 3
// speedup vs baseline: 1.5272x; 1.1981x over previous
#include <cuda_runtime.h>
#include <math.h>

#define NN 100000
#define NE 1600000
#define DIM 128
#define NB 391   // ceil(NN/256)

typedef unsigned long long ull;

// ---- scratch (device globals: no allocation allowed) ----
__device__ float g_xs[NN*DIM];    // source-side projection x@Wsrc
__device__ float g_h [NN*DIM];    // skip (x@linW+lin_b), later h
__device__ float g_x [NN*DIM];    // layer output ping buffer
__device__ float g_s [NN*8];      // per-node attention scores [ssrc0..3, sdst0..3]
__device__ float g_B [DIM*256];   // packed [Wsrc | linW]
__device__ float g_Batt[8*DIM];   // packed (W @ att) vectors, transposed
__device__ float g_bn [2*DIM];    // per-channel sum / sumsq
// CSR (built once per launch; graph fixed across layers)
__device__ int g_deg[NN];
__device__ int g_off[NN+1];
__device__ int g_pos[NN];
__device__ int g_csr[NE];
__device__ int g_bsum[NB];
__device__ int g_bbase[NB];

__device__ __forceinline__ void ffma2(ull &d, ull a, ull b) {
  asm volatile("fma.rn.f32x2 %0, %1, %2, %0;" : "+l"(d) : "l"(a), "l"(b));
}
__device__ __forceinline__ ull dup2(float v) {
  ull r; asm("mov.b64 %0, {%1, %1};" : "=l"(r) : "f"(v)); return r;
}
__device__ __forceinline__ void unpack2(float &lo, float &hi, ull v) {
  asm("mov.b64 {%0, %1}, %2;" : "=f"(lo), "=f"(hi) : "l"(v));
}

// ==================== CSR build ====================
__global__ void k_zero_deg() {
  int i = blockIdx.x*blockDim.x + threadIdx.x;
  if (i < NN) g_deg[i] = 0;
}
__global__ void k_hist(const int* __restrict__ dst) {
  int e = blockIdx.x*blockDim.x + threadIdx.x;
  if (e < NE) atomicAdd(&g_deg[dst[e]], 1);
}
__global__ void k_blockred() {
  __shared__ int sh[256];
  int t = threadIdx.x;
  int i = blockIdx.x*256 + t;
  sh[t] = (i < NN) ? g_deg[i] : 0;
  __syncthreads();
  for (int o = 128; o; o >>= 1) { if (t < o) sh[t] += sh[t+o]; __syncthreads(); }
  if (t == 0) g_bsum[blockIdx.x] = sh[0];
}
__global__ void k_scanb() {
  __shared__ int sh[512];
  int t = threadIdx.x;
  sh[t] = (t < NB) ? g_bsum[t] : 0;
  __syncthreads();
  for (int off = 1; off < 512; off <<= 1) {
    int v = 0;
    if (t >= off) v = sh[t-off];
    __syncthreads();
    sh[t] += v;
    __syncthreads();
  }
  if (t < NB) g_bbase[t] = sh[t] - g_bsum[t];   // exclusive
}
__global__ void k_off() {
  __shared__ int sh[256];
  int t = threadIdx.x;
  int i = blockIdx.x*256 + t;
  int v = (i < NN) ? g_deg[i] : 0;
  sh[t] = v;
  __syncthreads();
  for (int off = 1; off < 256; off <<= 1) {
    int u = 0;
    if (t >= off) u = sh[t-off];
    __syncthreads();
    sh[t] += u;
    __syncthreads();
  }
  int excl = sh[t] - v + g_bbase[blockIdx.x];
  if (i < NN) { g_off[i] = excl; g_pos[i] = excl; }
  if (i == NN-1) g_off[NN] = excl + v;
}
__global__ void k_scatter(const int* __restrict__ src, const int* __restrict__ dst) {
  int e = blockIdx.x*blockDim.x + threadIdx.x;
  if (e >= NE) return;
  int p = atomicAdd(&g_pos[dst[e]], 1);
  g_csr[p] = src[e];
}

// ---- pack per-layer weights (+ zero BN accumulators) ----
__global__ void pack_weights(const float* __restrict__ Wsrc,
                             const float* __restrict__ Wdst,
                             const float* __restrict__ linW,
                             const float* __restrict__ asrc,
                             const float* __restrict__ adst) {
  int idx = blockIdx.x*blockDim.x + threadIdx.x;
  if (idx < DIM*256) {
    int k = idx >> 8, j = idx & 255;
    g_B[idx] = (j < 128) ? Wsrc[k*128 + j] : linW[k*128 + (j-128)];
  } else if (idx < DIM*256 + 8*DIM) {
    int r = idx - DIM*256;
    int t = r >> 7, k = r & 127;
    int h = t & 3;
    const float* W = (t < 4) ? Wsrc : Wdst;
    const float* a = (t < 4) ? asrc : adst;
    float s = 0.f;
    #pragma unroll
    for (int c = 0; c < 32; c++) s += W[k*128 + h*32 + c] * a[h*32 + c];
    g_Batt[t*128 + k] = s;
  } else if (idx < DIM*256 + 8*DIM + 2*DIM) {
    g_bn[idx - (DIM*256 + 8*DIM)] = 0.f;
  }
}

// ---- fp32 SGEMM via packed fma.rn.f32x2: 128x128 tile, 8x8 per thread ----
__global__ void __launch_bounds__(256) sgemm(
    const float* __restrict__ A, const float* __restrict__ B,
    float* __restrict__ C, int M, int NC,
    const float* __restrict__ bias, int mode)
{
  __shared__ float As[16][128];
  __shared__ float Bs[16][128];
  const int tid = threadIdx.x;
  const int m0 = blockIdx.y * 128;
  const int n0 = blockIdx.x * 128;
  const int ty = tid >> 4, tx = tid & 15;

  ull acc2[8][4];
#pragma unroll
  for (int i = 0; i < 8; i++)
#pragma unroll
    for (int j = 0; j < 4; j++) acc2[i][j] = 0ull;

  const int aRow = tid >> 1;
  const int aK   = (tid & 1) * 8;
  const int bRow = tid >> 4;
  const int bCol = (tid & 15) * 8;

  for (int k0 = 0; k0 < 128; k0 += 16) {
    float4 a0, a1;
    if (m0 + aRow < M) {
      const float* ap = A + (size_t)(m0 + aRow)*128 + k0 + aK;
      a0 = *(const float4*)ap; a1 = *(const float4*)(ap + 4);
    } else { a0 = make_float4(0,0,0,0); a1 = a0; }
    As[aK+0][aRow]=a0.x; As[aK+1][aRow]=a0.y; As[aK+2][aRow]=a0.z; As[aK+3][aRow]=a0.w;
    As[aK+4][aRow]=a1.x; As[aK+5][aRow]=a1.y; As[aK+6][aRow]=a1.z; As[aK+7][aRow]=a1.w;

    const float* bp = B + (size_t)(k0 + bRow)*NC + n0 + bCol;
    float bv[8];
#pragma unroll
    for (int q = 0; q < 8; q++)
      bv[q] = (n0 + bCol + q < NC) ? bp[q] : 0.f;
    Bs[bRow][bCol+0]=bv[0]; Bs[bRow][bCol+1]=bv[1]; Bs[bRow][bCol+2]=bv[2]; Bs[bRow][bCol+3]=bv[3];
    Bs[bRow][bCol+4]=bv[4]; Bs[bRow][bCol+5]=bv[5]; Bs[bRow][bCol+6]=bv[6]; Bs[bRow][bCol+7]=bv[7];
    __syncthreads();

#pragma unroll
    for (int k = 0; k < 16; k++) {
      float4 t0 = *(const float4*)&As[k][ty*8];
      float4 t1 = *(const float4*)&As[k][ty*8+4];
      ull a2[8];
      a2[0]=dup2(t0.x); a2[1]=dup2(t0.y); a2[2]=dup2(t0.z); a2[3]=dup2(t0.w);
      a2[4]=dup2(t1.x); a2[5]=dup2(t1.y); a2[6]=dup2(t1.z); a2[7]=dup2(t1.w);
      ull bw2[4];
      bw2[0] = *(const ull*)&Bs[k][tx*8 + 0];
      bw2[1] = *(const ull*)&Bs[k][tx*8 + 2];
      bw2[2] = *(const ull*)&Bs[k][tx*8 + 4];
      bw2[3] = *(const ull*)&Bs[k][tx*8 + 6];
#pragma unroll
      for (int i = 0; i < 8; i++)
#pragma unroll
        for (int j = 0; j < 4; j++)
          ffma2(acc2[i][j], a2[i], bw2[j]);
    }
    __syncthreads();
  }

#pragma unroll
  for (int i = 0; i < 8; i++) {
    int r = m0 + ty*8 + i;
    if (r >= M) continue;
#pragma unroll
    for (int j = 0; j < 4; j++) {
      float vlo, vhi;
      unpack2(vlo, vhi, acc2[i][j]);
      int c = n0 + tx*8 + 2*j;
#pragma unroll
      for (int q = 0; q < 2; q++) {
        int cc = c + q;
        if (cc >= NC) continue;
        float v = q ? vhi : vlo;
        if (mode == 0) {
          C[(size_t)r*NC + cc] = v + bias[cc];
        } else {
          if (cc < 128) g_xs[(size_t)r*128 + cc] = v;
          else          g_h [(size_t)r*128 + (cc-128)] = v + bias[cc-128];
        }
      }
    }
  }
}

// ---- per-node attention scores: s[n,t] = x[n,:] @ g_Batt[t,:] ----
__global__ void __launch_bounds__(256) att_scores(const float* __restrict__ X) {
  int gw = (blockIdx.x*blockDim.x + threadIdx.x) >> 5;
  if (gw >= NN) return;
  int lane = threadIdx.x & 31;
  float4 xv = *(const float4*)&X[(size_t)gw*128 + lane*4];
#pragma unroll
  for (int t = 0; t < 8; t++) {
    float4 w = *(const float4*)&g_Batt[t*128 + lane*4];
    float p = xv.x*w.x + xv.y*w.y + xv.z*w.z + xv.w*w.w;
#pragma unroll
    for (int off = 16; off; off >>= 1) p += __shfl_xor_sync(0xffffffffu, p, off);
    if (lane == 0) g_s[(size_t)gw*8 + t] = p;
  }
}

// ---- gather: per-dst softmax + aggregate + conv_bias + skip + BN stats ----
// warp per node; no atomics on feature data.
__global__ void __launch_bounds__(256) gather_combine(const float* __restrict__ cbias) {
  __shared__ float s_sum[128], s_sq[128];
  int tid = threadIdx.x;
  if (tid < 128) { s_sum[tid] = 0.f; s_sq[tid] = 0.f; }
  __syncthreads();
  int warp = tid >> 5, lane = tid & 31;
  int n = blockIdx.x*8 + warp;
  int head = lane >> 3, c4 = lane*4;
  float h0=0,h1=0,h2=0,h3=0;
  bool valid = (n < NN);
  if (valid) {
    int beg = g_off[n], end = g_off[n+1];
    float sd = g_s[(size_t)n*8 + 4 + head];
    float ax=0.f, ay=0.f, az=0.f, aw=0.f, den=0.f;
    for (int i = beg; i < end; i++) {
      int s = g_csr[i];
      float ev = g_s[(size_t)s*8 + head] + sd;
      ev = (ev > 0.f) ? ev : 0.2f*ev;
      float p = __expf(ev);
      den += p;
      float4 v = *(const float4*)&g_xs[(size_t)s*128 + c4];
      ax = fmaf(v.x, p, ax); ay = fmaf(v.y, p, ay);
      az = fmaf(v.z, p, az); aw = fmaf(v.w, p, aw);
    }
    float inv = 1.f / (den + 1e-16f);
    float4 cb = *(const float4*)&cbias[c4];
    float4 sk = *(const float4*)&g_h[(size_t)n*128 + c4];
    h0 = ax*inv + cb.x + sk.x;
    h1 = ay*inv + cb.y + sk.y;
    h2 = az*inv + cb.z + sk.z;
    h3 = aw*inv + cb.w + sk.w;
    *(float4*)&g_h[(size_t)n*128 + c4] = make_float4(h0,h1,h2,h3);
  }
  // BN stats: shared reduce across the 8 warps, then 128 global REDs
  if (valid) {
    atomicAdd(&s_sum[c4+0], h0); atomicAdd(&s_sum[c4+1], h1);
    atomicAdd(&s_sum[c4+2], h2); atomicAdd(&s_sum[c4+3], h3);
    atomicAdd(&s_sq[c4+0], h0*h0); atomicAdd(&s_sq[c4+1], h1*h1);
    atomicAdd(&s_sq[c4+2], h2*h2); atomicAdd(&s_sq[c4+3], h3*h3);
  }
  __syncthreads();
  if (tid < 128) {
    atomicAdd(&g_bn[tid],       s_sum[tid]);
    atomicAdd(&g_bn[128 + tid], s_sq[tid]);
  }
}

// ---- batchnorm + relu ----
__global__ void __launch_bounds__(256) bn_relu(const float* __restrict__ gamma,
                                               const float* __restrict__ beta,
                                               float* __restrict__ XO) {
  int idx = blockIdx.x*blockDim.x + threadIdx.x;
  if (idx >= NN*32) return;
  int c4 = (idx & 31) * 4;
  const float invN = 1.f / (float)NN;
  float4 h = *(const float4*)&g_h[(size_t)idx*4];
  float hv[4] = {h.x, h.y, h.z, h.w};
  float ov[4];
#pragma unroll
  for (int k = 0; k < 4; k++) {
    int c = c4 + k;
    float mu  = g_bn[c] * invN;
    float var = g_bn[128 + c] * invN - mu*mu;
    float sc  = gamma[c] * rsqrtf(var + 1e-5f);
    float sh  = beta[c] - mu*sc;
    float v = hv[k]*sc + sh;
    ov[k] = v > 0.f ? v : 0.f;
  }
  *(float4*)&XO[(size_t)idx*4] = make_float4(ov[0],ov[1],ov[2],ov[3]);
}

extern "C" void kernel_launch(void* const* d_in, const int* in_sizes, int n_in,
                              void* d_out, int out_size) {
  const float* x0    = (const float*)d_in[0];
  const int*   ei    = (const int*)  d_in[1];
  const float* Wsrc  = (const float*)d_in[2];
  const float* Wdst  = (const float*)d_in[3];
  const float* asrc  = (const float*)d_in[4];
  const float* adst  = (const float*)d_in[5];
  const float* cbias = (const float*)d_in[6];
  const float* linW  = (const float*)d_in[7];
  const float* linb  = (const float*)d_in[8];
  const float* gamma = (const float*)d_in[9];
  const float* beta  = (const float*)d_in[10];
  const float* fcW   = (const float*)d_in[11];
  const float* fcb   = (const float*)d_in[12];
  float* out = (float*)d_out;

  float *xg = 0, *Bg = 0;
  cudaGetSymbolAddress((void**)&xg, g_x);
  cudaGetSymbolAddress((void**)&Bg, g_B);

  const int* src = ei;
  const int* dst = ei + NE;

  // ---- CSR build (once; graph shared by both layers) ----
  k_zero_deg<<<NB, 256>>>();
  k_hist<<<(NE+255)/256, 256>>>(dst);
  k_blockred<<<NB, 256>>>();
  k_scanb<<<1, 512>>>();
  k_off<<<NB, 256>>>();
  k_scatter<<<(NE+255)/256, 256>>>(src, dst);

  for (int i = 0; i < 2; i++) {
    const float* xin = (i == 0) ? x0 : xg;
    pack_weights<<<134, 256>>>(Wsrc + i*16384, Wdst + i*16384, linW + i*16384,
                               asrc + i*128, adst + i*128);
    sgemm<<<dim3(2, 782), 256>>>(xin, Bg, nullptr, NN, 256, linb + i*128, 1);
    att_scores<<<12500, 256>>>(xin);
    gather_combine<<<12500, 256>>>(cbias + i*128);
    bn_relu<<<12500, 256>>>(gamma + i*128, beta + i*128, xg);
  }
  sgemm<<<dim3(3, 782), 256>>>(xg, fcW, out, NN, 349, fcb, 0);
}

// round 5
// speedup vs baseline: 1.9067x; 1.2485x over previous
#include <cuda_runtime.h>
#include <cuda_bf16.h>
#include <math.h>
#include <stdint.h>

#define NN 100000
#define NE 1600000
#define DIM 128
#define NB 391   // ceil(NN/256)

typedef unsigned long long ull;

// ---- scratch (device globals: no allocation allowed) ----
__device__ __nv_bfloat16 g_xs[NN*DIM];  // source-side projection x@Wsrc (bf16)
__device__ float g_h [NN*DIM];    // skip (x@linW+lin_b), later h
__device__ float g_x [NN*DIM];    // layer output ping buffer
__device__ float g_s [NN*8];      // per-node attention scores [ssrc0..3, sdst0..3]
__device__ float g_B [DIM*256];   // packed [Wsrc | linW], [k][n]
__device__ float g_Batt[8*DIM];   // packed (W @ att) vectors
__device__ float g_bn [2*DIM];    // per-channel sum / sumsq
// CSR (built once; graph fixed across layers)
__device__ int g_deg[NN];
__device__ int g_off[NN+1];
__device__ int g_pos[NN];
__device__ int g_csr[NE];
__device__ int g_bsum[NB];
__device__ int g_bbase[NB];

__device__ __forceinline__ void ffma2(ull &d, ull a, ull b) {
  asm volatile("fma.rn.f32x2 %0, %1, %2, %0;" : "+l"(d) : "l"(a), "l"(b));
}
__device__ __forceinline__ ull dup2(float v) {
  ull r; asm("mov.b64 %0, {%1, %1};" : "=l"(r) : "f"(v)); return r;
}
__device__ __forceinline__ void unpack2(float &lo, float &hi, ull v) {
  asm("mov.b64 {%0, %1}, %2;" : "=f"(lo), "=f"(hi) : "l"(v));
}

// ==================== CSR build ====================
__global__ void k_zero_deg() {
  int i = blockIdx.x*blockDim.x + threadIdx.x;
  if (i < NN) g_deg[i] = 0;
}
__global__ void k_hist(const int* __restrict__ dst) {
  int e = blockIdx.x*blockDim.x + threadIdx.x;
  if (e < NE) atomicAdd(&g_deg[dst[e]], 1);
}
__global__ void k_blockred() {
  __shared__ int sh[256];
  int t = threadIdx.x;
  int i = blockIdx.x*256 + t;
  sh[t] = (i < NN) ? g_deg[i] : 0;
  __syncthreads();
  for (int o = 128; o; o >>= 1) { if (t < o) sh[t] += sh[t+o]; __syncthreads(); }
  if (t == 0) g_bsum[blockIdx.x] = sh[0];
}
__global__ void k_scanb() {
  __shared__ int sh[512];
  int t = threadIdx.x;
  sh[t] = (t < NB) ? g_bsum[t] : 0;
  __syncthreads();
  for (int off = 1; off < 512; off <<= 1) {
    int v = 0;
    if (t >= off) v = sh[t-off];
    __syncthreads();
    sh[t] += v;
    __syncthreads();
  }
  if (t < NB) g_bbase[t] = sh[t] - g_bsum[t];   // exclusive
}
__global__ void k_off() {
  __shared__ int sh[256];
  int t = threadIdx.x;
  int i = blockIdx.x*256 + t;
  int v = (i < NN) ? g_deg[i] : 0;
  sh[t] = v;
  __syncthreads();
  for (int off = 1; off < 256; off <<= 1) {
    int u = 0;
    if (t >= off) u = sh[t-off];
    __syncthreads();
    sh[t] += u;
    __syncthreads();
  }
  int excl = sh[t] - v + g_bbase[blockIdx.x];
  if (i < NN) { g_off[i] = excl; g_pos[i] = excl; }
  if (i == NN-1) g_off[NN] = excl + v;
}
__global__ void k_scatter(const int* __restrict__ src, const int* __restrict__ dst) {
  int e = blockIdx.x*blockDim.x + threadIdx.x;
  if (e >= NE) return;
  int p = atomicAdd(&g_pos[dst[e]], 1);
  g_csr[p] = src[e];
}

// ---- pack per-layer weights (+ zero BN accumulators) ----
__global__ void pack_weights(const float* __restrict__ Wsrc,
                             const float* __restrict__ Wdst,
                             const float* __restrict__ linW,
                             const float* __restrict__ asrc,
                             const float* __restrict__ adst) {
  int idx = blockIdx.x*blockDim.x + threadIdx.x;
  if (idx < DIM*256) {
    int k = idx >> 8, j = idx & 255;
    g_B[idx] = (j < 128) ? Wsrc[k*128 + j] : linW[k*128 + (j-128)];
  } else if (idx < DIM*256 + 8*DIM) {
    int r = idx - DIM*256;
    int t = r >> 7, k = r & 127;
    int h = t & 3;
    const float* W = (t < 4) ? Wsrc : Wdst;
    const float* a = (t < 4) ? asrc : adst;
    float s = 0.f;
    #pragma unroll
    for (int c = 0; c < 32; c++) s += W[k*128 + h*32 + c] * a[h*32 + c];
    g_Batt[t*128 + k] = s;
  } else if (idx < DIM*256 + 8*DIM + 2*DIM) {
    g_bn[idx - (DIM*256 + 8*DIM)] = 0.f;
  }
}

// ---- fp32 SGEMM via packed fma.rn.f32x2: 128x128 tile, 8x8 per thread ----
// thread columns: {tx*4..+3} and {64+tx*4..+3} (conflict-free LDS.64 on Bs)
// mode 0: C[r*NC+c] = acc + bias[c]
// mode 1: n0==0 -> g_xs (bf16) ; n0==128 -> g_h (+bias[c-128])
__global__ void __launch_bounds__(256) sgemm(
    const float* __restrict__ A, const float* __restrict__ B,
    float* __restrict__ C, int M, int NC,
    const float* __restrict__ bias, int mode)
{
  __shared__ float As[16][128];
  __shared__ float Bs[16][128];
  const int tid = threadIdx.x;
  const int m0 = blockIdx.y * 128;
  const int n0 = blockIdx.x * 128;
  const int ty = tid >> 4, tx = tid & 15;

  ull acc2[8][4];
#pragma unroll
  for (int i = 0; i < 8; i++)
#pragma unroll
    for (int j = 0; j < 4; j++) acc2[i][j] = 0ull;

  const int aRow = tid >> 1;
  const int aK   = (tid & 1) * 8;
  const int bRow = tid >> 4;
  const int bCol = (tid & 15) * 8;

  for (int k0 = 0; k0 < 128; k0 += 16) {
    float4 a0, a1;
    if (m0 + aRow < M) {
      const float* ap = A + (size_t)(m0 + aRow)*128 + k0 + aK;
      a0 = *(const float4*)ap; a1 = *(const float4*)(ap + 4);
    } else { a0 = make_float4(0,0,0,0); a1 = a0; }
    As[aK+0][aRow]=a0.x; As[aK+1][aRow]=a0.y; As[aK+2][aRow]=a0.z; As[aK+3][aRow]=a0.w;
    As[aK+4][aRow]=a1.x; As[aK+5][aRow]=a1.y; As[aK+6][aRow]=a1.z; As[aK+7][aRow]=a1.w;

    const float* bp = B + (size_t)(k0 + bRow)*NC + n0 + bCol;
    float bv[8];
#pragma unroll
    for (int q = 0; q < 8; q++)
      bv[q] = (n0 + bCol + q < NC) ? bp[q] : 0.f;
    Bs[bRow][bCol+0]=bv[0]; Bs[bRow][bCol+1]=bv[1]; Bs[bRow][bCol+2]=bv[2]; Bs[bRow][bCol+3]=bv[3];
    Bs[bRow][bCol+4]=bv[4]; Bs[bRow][bCol+5]=bv[5]; Bs[bRow][bCol+6]=bv[6]; Bs[bRow][bCol+7]=bv[7];
    __syncthreads();

#pragma unroll
    for (int k = 0; k < 16; k++) {
      float4 t0 = *(const float4*)&As[k][ty*8];
      float4 t1 = *(const float4*)&As[k][ty*8+4];
      ull a2[8];
      a2[0]=dup2(t0.x); a2[1]=dup2(t0.y); a2[2]=dup2(t0.z); a2[3]=dup2(t0.w);
      a2[4]=dup2(t1.x); a2[5]=dup2(t1.y); a2[6]=dup2(t1.z); a2[7]=dup2(t1.w);
      ull bw2[4];
      bw2[0] = *(const ull*)&Bs[k][tx*4 + 0];
      bw2[1] = *(const ull*)&Bs[k][tx*4 + 2];
      bw2[2] = *(const ull*)&Bs[k][64 + tx*4 + 0];
      bw2[3] = *(const ull*)&Bs[k][64 + tx*4 + 2];
#pragma unroll
      for (int i = 0; i < 8; i++)
#pragma unroll
        for (int j = 0; j < 4; j++)
          ffma2(acc2[i][j], a2[i], bw2[j]);
    }
    __syncthreads();
  }

#pragma unroll
  for (int i = 0; i < 8; i++) {
    int r = m0 + ty*8 + i;
    if (r >= M) continue;
#pragma unroll
    for (int j = 0; j < 4; j++) {
      float vlo, vhi;
      unpack2(vlo, vhi, acc2[i][j]);
      int cl = (j < 2) ? (tx*4 + 2*j) : (64 + tx*4 + 2*(j-2));  // local col
      int c = n0 + cl;
      if (mode == 0) {
        if (c < NC)   C[(size_t)r*NC + c]     = vlo + bias[c];
        if (c+1 < NC) C[(size_t)r*NC + c + 1] = vhi + bias[c+1];
      } else if (n0 == 0) {
        __nv_bfloat162 bb = __float22bfloat162_rn(make_float2(vlo, vhi));
        *(__nv_bfloat162*)&g_xs[(size_t)r*128 + cl] = bb;
      } else {
        g_h[(size_t)r*128 + cl]     = vlo + bias[cl];
        g_h[(size_t)r*128 + cl + 1] = vhi + bias[cl + 1];
      }
    }
  }
}

// ---- per-node attention scores ----
__global__ void __launch_bounds__(256) att_scores(const float* __restrict__ X) {
  int gw = (blockIdx.x*blockDim.x + threadIdx.x) >> 5;
  if (gw >= NN) return;
  int lane = threadIdx.x & 31;
  float4 xv = *(const float4*)&X[(size_t)gw*128 + lane*4];
#pragma unroll
  for (int t = 0; t < 8; t++) {
    float4 w = *(const float4*)&g_Batt[t*128 + lane*4];
    float p = xv.x*w.x + xv.y*w.y + xv.z*w.z + xv.w*w.w;
#pragma unroll
    for (int off = 16; off; off >>= 1) p += __shfl_xor_sync(0xffffffffu, p, off);
    if (lane == 0) g_s[(size_t)gw*8 + t] = p;
  }
}

// ---- gather: per-dst softmax + aggregate + conv_bias + skip + BN stats ----
// warp per node; bf16 message operand halves L2 gather traffic.
__global__ void __launch_bounds__(256) gather_combine(const float* __restrict__ cbias) {
  __shared__ float s_sum[128], s_sq[128];
  int tid = threadIdx.x;
  if (tid < 128) { s_sum[tid] = 0.f; s_sq[tid] = 0.f; }
  __syncthreads();
  int warp = tid >> 5, lane = tid & 31;
  int n = blockIdx.x*8 + warp;
  int head = lane >> 3, c4 = lane*4;
  float h0=0,h1=0,h2=0,h3=0;
  bool valid = (n < NN);
  if (valid) {
    int beg = g_off[n], end = g_off[n+1];
    float sd = g_s[(size_t)n*8 + 4 + head];
    float ax=0.f, ay=0.f, az=0.f, aw=0.f, den=0.f;
    for (int i = beg; i < end; i++) {
      int s = g_csr[i];
      float ev = g_s[(size_t)s*8 + head] + sd;
      ev = (ev > 0.f) ? ev : 0.2f*ev;
      float p = __expf(ev);
      den += p;
      uint2 u = *(const uint2*)&g_xs[(size_t)s*128 + c4];
      float2 f0 = __bfloat1622float2(*reinterpret_cast<__nv_bfloat162*>(&u.x));
      float2 f1 = __bfloat1622float2(*reinterpret_cast<__nv_bfloat162*>(&u.y));
      ax = fmaf(f0.x, p, ax); ay = fmaf(f0.y, p, ay);
      az = fmaf(f1.x, p, az); aw = fmaf(f1.y, p, aw);
    }
    float inv = 1.f / (den + 1e-16f);
    float4 cb = *(const float4*)&cbias[c4];
    float4 sk = *(const float4*)&g_h[(size_t)n*128 + c4];
    h0 = ax*inv + cb.x + sk.x;
    h1 = ay*inv + cb.y + sk.y;
    h2 = az*inv + cb.z + sk.z;
    h3 = aw*inv + cb.w + sk.w;
    *(float4*)&g_h[(size_t)n*128 + c4] = make_float4(h0,h1,h2,h3);
  }
  if (valid) {
    atomicAdd(&s_sum[c4+0], h0); atomicAdd(&s_sum[c4+1], h1);
    atomicAdd(&s_sum[c4+2], h2); atomicAdd(&s_sum[c4+3], h3);
    atomicAdd(&s_sq[c4+0], h0*h0); atomicAdd(&s_sq[c4+1], h1*h1);
    atomicAdd(&s_sq[c4+2], h2*h2); atomicAdd(&s_sq[c4+3], h3*h3);
  }
  __syncthreads();
  if (tid < 128) {
    atomicAdd(&g_bn[tid],       s_sum[tid]);
    atomicAdd(&g_bn[128 + tid], s_sq[tid]);
  }
}

// ---- batchnorm + relu ----
__global__ void __launch_bounds__(256) bn_relu(const float* __restrict__ gamma,
                                               const float* __restrict__ beta,
                                               float* __restrict__ XO) {
  int idx = blockIdx.x*blockDim.x + threadIdx.x;
  if (idx >= NN*32) return;
  int c4 = (idx & 31) * 4;
  const float invN = 1.f / (float)NN;
  float4 h = *(const float4*)&g_h[(size_t)idx*4];
  float hv[4] = {h.x, h.y, h.z, h.w};
  float ov[4];
#pragma unroll
  for (int k = 0; k < 4; k++) {
    int c = c4 + k;
    float mu  = g_bn[c] * invN;
    float var = g_bn[128 + c] * invN - mu*mu;
    float sc  = gamma[c] * rsqrtf(var + 1e-5f);
    float sh  = beta[c] - mu*sc;
    float v = hv[k]*sc + sh;
    ov[k] = v > 0.f ? v : 0.f;
  }
  *(float4*)&XO[(size_t)idx*4] = make_float4(ov[0],ov[1],ov[2],ov[3]);
}

extern "C" void kernel_launch(void* const* d_in, const int* in_sizes, int n_in,
                              void* d_out, int out_size) {
  const float* x0    = (const float*)d_in[0];
  const int*   ei    = (const int*)  d_in[1];
  const float* Wsrc  = (const float*)d_in[2];
  const float* Wdst  = (const float*)d_in[3];
  const float* asrc  = (const float*)d_in[4];
  const float* adst  = (const float*)d_in[5];
  const float* cbias = (const float*)d_in[6];
  const float* linW  = (const float*)d_in[7];
  const float* linb  = (const float*)d_in[8];
  const float* gamma = (const float*)d_in[9];
  const float* beta  = (const float*)d_in[10];
  const float* fcW   = (const float*)d_in[11];
  const float* fcb   = (const float*)d_in[12];
  float* out = (float*)d_out;

  float *xg = 0, *Bg = 0;
  cudaGetSymbolAddress((void**)&xg, g_x);
  cudaGetSymbolAddress((void**)&Bg, g_B);

  const int* src = ei;
  const int* dst = ei + NE;

  // order: launch index 3 (profiled by ncu) = layer-1 projection sgemm
  k_zero_deg<<<NB, 256>>>();
  k_hist<<<(NE+255)/256, 256>>>(dst);
  pack_weights<<<134, 256>>>(Wsrc, Wdst, linW, asrc, adst);
  sgemm<<<dim3(2, 782), 256>>>(x0, Bg, nullptr, NN, 256, linb, 1);   // <- profiled
  k_blockred<<<NB, 256>>>();
  k_scanb<<<1, 512>>>();
  k_off<<<NB, 256>>>();
  k_scatter<<<(NE+255)/256, 256>>>(src, dst);
  att_scores<<<12500, 256>>>(x0);
  gather_combine<<<12500, 256>>>(cbias);
  bn_relu<<<12500, 256>>>(gamma, beta, xg);

  pack_weights<<<134, 256>>>(Wsrc + 16384, Wdst + 16384, linW + 16384,
                             asrc + 128, adst + 128);
  sgemm<<<dim3(2, 782), 256>>>(xg, Bg, nullptr, NN, 256, linb + 128, 1);
  att_scores<<<12500, 256>>>(xg);
  gather_combine<<<12500, 256>>>(cbias + 128);
  bn_relu<<<12500, 256>>>(gamma + 128, beta + 128, xg);

  sgemm<<<dim3(3, 782), 256>>>(xg, fcW, out, NN, 349, fcb, 0);
}